// round 1
// baseline (speedup 1.0000x reference)
#include <cuda_runtime.h>
#include <math.h>
#include <stdint.h>
#include <stddef.h>

// ---------------- problem dims ----------------
#define NB   100      // nodes / batch
#define TT   512      // time steps
#define IND  256      // input dim
#define HD   1024     // hidden
#define H3   3072     // 3*H

// ---------------- scratch (device globals; no allocation allowed) ----------------
__device__ float g_xp[(size_t)NB * TT * H3];     // 629 MB: xp, later reused as attention scores w
__device__ float g_hs[(size_t)NB * TT * HD];     // 210 MB: all hidden states
__device__ float g_v[NB * HD];
__device__ float g_hp[NB * HD];
__device__ float g_inner[NB * HD];
__device__ float g_catv[5 * HD];
__device__ float g_hp2[5 * HD];
__device__ float g_cat[5 * HD];
__device__ float g_as[NB];
__device__ float g_ad[NB];
__device__ float g_as2[8];
__device__ float g_ad2[8];
__device__ float g_fin[NB * H3];
__device__ float g_f[NB * HD];

// =================================================================
// Generic tiled SGEMM:  C[M,N] = A[M,K] @ B[N,K]^T (+ bias[N]) (+relu)
// A row-major MxK, B row-major NxK. 128x128 tile, BK=16, 256 thr, 8x8 micro.
// Requires K % 16 == 0.
// =================================================================
__global__ __launch_bounds__(256) void gemm_nt(
    const float* __restrict__ A, const float* __restrict__ B,
    const float* __restrict__ bias, float* __restrict__ C,
    int M, int N, int K, int act)
{
    __shared__ float As[16][128];
    __shared__ float Bs[16][128];
    int tid = threadIdx.x;
    int tx = tid & 15, ty = tid >> 4;
    int row0 = blockIdx.y * 128, col0 = blockIdx.x * 128;

    float acc[8][8];
#pragma unroll
    for (int i = 0; i < 8; i++)
#pragma unroll
        for (int j = 0; j < 8; j++) acc[i][j] = 0.f;

    int lr = tid >> 2;   // 0..63
    int lc = tid & 3;    // k-offset group

    for (int k0 = 0; k0 < K; k0 += 16) {
#pragma unroll
        for (int p = 0; p < 2; p++) {
            int r = lr + p * 64;
            int gr = row0 + r;
            float4 v = make_float4(0.f, 0.f, 0.f, 0.f);
            if (gr < M) v = *(const float4*)(A + (size_t)gr * K + k0 + lc * 4);
            As[lc * 4 + 0][r] = v.x; As[lc * 4 + 1][r] = v.y;
            As[lc * 4 + 2][r] = v.z; As[lc * 4 + 3][r] = v.w;
        }
#pragma unroll
        for (int p = 0; p < 2; p++) {
            int r = lr + p * 64;
            int gc = col0 + r;
            float4 v = make_float4(0.f, 0.f, 0.f, 0.f);
            if (gc < N) v = *(const float4*)(B + (size_t)gc * K + k0 + lc * 4);
            Bs[lc * 4 + 0][r] = v.x; Bs[lc * 4 + 1][r] = v.y;
            Bs[lc * 4 + 2][r] = v.z; Bs[lc * 4 + 3][r] = v.w;
        }
        __syncthreads();
#pragma unroll
        for (int kk = 0; kk < 16; kk++) {
            float a[8], b[8];
            *(float4*)&a[0] = *(const float4*)&As[kk][ty * 8];
            *(float4*)&a[4] = *(const float4*)&As[kk][ty * 8 + 4];
            *(float4*)&b[0] = *(const float4*)&Bs[kk][tx * 8];
            *(float4*)&b[4] = *(const float4*)&Bs[kk][tx * 8 + 4];
#pragma unroll
            for (int i = 0; i < 8; i++)
#pragma unroll
                for (int j = 0; j < 8; j++) acc[i][j] += a[i] * b[j];
        }
        __syncthreads();
    }

#pragma unroll
    for (int i = 0; i < 8; i++) {
        int gm = row0 + ty * 8 + i;
        if (gm >= M) continue;
#pragma unroll
        for (int j = 0; j < 8; j++) {
            int gn = col0 + tx * 8 + j;
            if (gn >= N) continue;
            float v = acc[i][j];
            if (bias) v += bias[gn];
            if (act == 1) v = fmaxf(v, 0.f);
            C[(size_t)gm * N + gn] = v;
        }
    }
}

// =================================================================
// Batched NN GEMM for enc attention:
//   C_b[u,d] = sum_t A[u,t] * B_b[t,d]  + rowbias[u]
// A: MxK shared across batch; B_b = Bbase + z*strideB (KxN); C likewise.
// M,N multiples of 128; K multiple of 16.
// =================================================================
__global__ __launch_bounds__(256) void gemm_nn_batched(
    const float* __restrict__ A, const float* __restrict__ Bbase,
    const float* __restrict__ rowbias, float* __restrict__ Cbase,
    int M, int N, int K, size_t strideB, size_t strideC)
{
    const float* B = Bbase + (size_t)blockIdx.z * strideB;
    float* C = Cbase + (size_t)blockIdx.z * strideC;
    __shared__ float As[16][128];
    __shared__ float Bs[16][128];
    int tid = threadIdx.x;
    int tx = tid & 15, ty = tid >> 4;
    int row0 = blockIdx.y * 128, col0 = blockIdx.x * 128;

    float acc[8][8];
#pragma unroll
    for (int i = 0; i < 8; i++)
#pragma unroll
        for (int j = 0; j < 8; j++) acc[i][j] = 0.f;

    int lr = tid >> 2;
    int lc = tid & 3;
    int br = tid >> 5;       // 0..7
    int bc = tid & 31;       // 0..31

    for (int k0 = 0; k0 < K; k0 += 16) {
#pragma unroll
        for (int p = 0; p < 2; p++) {
            int r = lr + p * 64;
            int gr = row0 + r;
            float4 v = make_float4(0.f, 0.f, 0.f, 0.f);
            if (gr < M) v = *(const float4*)(A + (size_t)gr * K + k0 + lc * 4);
            As[lc * 4 + 0][r] = v.x; As[lc * 4 + 1][r] = v.y;
            As[lc * 4 + 2][r] = v.z; As[lc * 4 + 3][r] = v.w;
        }
#pragma unroll
        for (int p = 0; p < 2; p++) {
            int k = br + p * 8;
            float4 v = *(const float4*)(B + (size_t)(k0 + k) * N + col0 + bc * 4);
            *(float4*)&Bs[k][bc * 4] = v;
        }
        __syncthreads();
#pragma unroll
        for (int kk = 0; kk < 16; kk++) {
            float a[8], b[8];
            *(float4*)&a[0] = *(const float4*)&As[kk][ty * 8];
            *(float4*)&a[4] = *(const float4*)&As[kk][ty * 8 + 4];
            *(float4*)&b[0] = *(const float4*)&Bs[kk][tx * 8];
            *(float4*)&b[4] = *(const float4*)&Bs[kk][tx * 8 + 4];
#pragma unroll
            for (int i = 0; i < 8; i++)
#pragma unroll
                for (int j = 0; j < 8; j++) acc[i][j] += a[i] * b[j];
        }
        __syncthreads();
    }

#pragma unroll
    for (int i = 0; i < 8; i++) {
        int gm = row0 + ty * 8 + i;
        float rb = rowbias[gm];
#pragma unroll
        for (int j = 0; j < 8; j++) {
            int gn = col0 + tx * 8 + j;
            C[(size_t)gm * N + gn] = acc[i][j] + rb;
        }
    }
}

// =================================================================
// One GRU time step. grid=128 blocks x 256 thr. warp w owns column
// c = blockIdx.x*8 + w; keeps Whh rows {c, H+c, 2H+c} in registers.
// Reads hs[:,t-1,:], xp[:,t,:], writes hs[:,t,:].
// =================================================================
__global__ __launch_bounds__(256) void gru_step(
    const float* __restrict__ xp, const float* __restrict__ Whh,
    const float* __restrict__ bhh, float* __restrict__ hs, int t)
{
    int warp = threadIdx.x >> 5;
    int lane = threadIdx.x & 31;
    int c = blockIdx.x * 8 + warp;       // 0..1023
    int ks = lane * 32;                  // this lane's contiguous K-slice

    float4 w0[8], w1[8], w2[8];
    {
        const float4* p0 = (const float4*)(Whh + (size_t)(0 * HD + c) * HD + ks);
        const float4* p1 = (const float4*)(Whh + (size_t)(1 * HD + c) * HD + ks);
        const float4* p2 = (const float4*)(Whh + (size_t)(2 * HD + c) * HD + ks);
#pragma unroll
        for (int j = 0; j < 8; j++) { w0[j] = p0[j]; w1[j] = p1[j]; w2[j] = p2[j]; }
    }
    float b0 = bhh[c], b1 = bhh[HD + c], b2 = bhh[2 * HD + c];

    for (int b = 0; b < NB; b++) {
        float a0 = 0.f, a1 = 0.f, a2 = 0.f;
        const float* hrow = hs + ((size_t)b * TT + (t - 1)) * HD;
        if (t > 0) {
            const float4* hp4 = (const float4*)(hrow + ks);
#pragma unroll
            for (int j = 0; j < 8; j++) {
                float4 h4 = hp4[j];
                a0 += h4.x * w0[j].x + h4.y * w0[j].y + h4.z * w0[j].z + h4.w * w0[j].w;
                a1 += h4.x * w1[j].x + h4.y * w1[j].y + h4.z * w1[j].z + h4.w * w1[j].w;
                a2 += h4.x * w2[j].x + h4.y * w2[j].y + h4.z * w2[j].z + h4.w * w2[j].w;
            }
        }
#pragma unroll
        for (int off = 16; off > 0; off >>= 1) {
            a0 += __shfl_down_sync(0xffffffffu, a0, off);
            a1 += __shfl_down_sync(0xffffffffu, a1, off);
            a2 += __shfl_down_sync(0xffffffffu, a2, off);
        }
        if (lane == 0) {
            size_t xi = ((size_t)b * TT + t) * H3;
            float xr = xp[xi + c];
            float xz = xp[xi + HD + c];
            float xn = xp[xi + 2 * HD + c];
            float r = 1.f / (1.f + expf(-(xr + a0 + b0)));
            float z = 1.f / (1.f + expf(-(xz + a1 + b1)));
            float n = tanhf(xn + r * (a2 + b2));
            float hold = (t > 0) ? hrow[c] : 0.f;
            hs[((size_t)b * TT + t) * HD + c] = (1.f - z) * n + z * hold;
        }
    }
}

// =================================================================
// Attention reduce over time:  out[b,d] = sum_u softmax_u(w[b,u,d]) * x[b,u,d]
// =================================================================
__global__ void att_reduce(const float* __restrict__ w, const float* __restrict__ x,
                           float* __restrict__ out, int U, int D)
{
    int b = blockIdx.x;
    int d = blockIdx.y * blockDim.x + threadIdx.x;
    const float* wb = w + (size_t)b * U * D;
    const float* xb = x + (size_t)b * U * D;
    float mx = -1e30f;
    for (int u = 0; u < U; u++) mx = fmaxf(mx, wb[(size_t)u * D + d]);
    float se = 0.f, sv = 0.f;
    for (int u = 0; u < U; u++) {
        float e = expf(wb[(size_t)u * D + d] - mx);
        se += e;
        sv += e * xb[(size_t)u * D + d];
    }
    out[(size_t)b * D + d] = sv / se;
}

// =================================================================
// Pool attention: 20 stocks -> 1 category vector (per category c)
// =================================================================
__global__ void pool_att(const float* __restrict__ v, const float* __restrict__ pW,
                         const float* __restrict__ pb, float* __restrict__ out)
{
    int c = blockIdx.x;
    int d = blockIdx.y * 256 + threadIdx.x;
    __shared__ float sW[400];
    __shared__ float sb[20];
    for (int i = threadIdx.x; i < 400; i += 256) sW[i] = pW[i];
    if (threadIdx.x < 20) sb[threadIdx.x] = pb[threadIdx.x];
    __syncthreads();

    float xv[20];
#pragma unroll
    for (int t = 0; t < 20; t++) xv[t] = v[(size_t)(c * 20 + t) * HD + d];
    float wv[20];
    float mx = -1e30f;
#pragma unroll
    for (int u = 0; u < 20; u++) {
        float s = sb[u];
#pragma unroll
        for (int t = 0; t < 20; t++) s += xv[t] * sW[u * 20 + t];
        wv[u] = s;
        mx = fmaxf(mx, s);
    }
    float se = 0.f, sv = 0.f;
#pragma unroll
    for (int u = 0; u < 20; u++) {
        float e = expf(wv[u] - mx);
        se += e;
        sv += e * xv[u];
    }
    out[(size_t)c * HD + d] = sv / se;
}

// two dot products per node: as[n]=h[n,:].a1, ad[n]=h[n,:].a2
__global__ void dot2(const float* __restrict__ h, const float* __restrict__ a1,
                     const float* __restrict__ a2, float* __restrict__ o1,
                     float* __restrict__ o2, int D)
{
    int n = blockIdx.x;
    __shared__ float s1[256], s2[256];
    float p1 = 0.f, p2 = 0.f;
    for (int k = threadIdx.x; k < D; k += 256) {
        float hv = h[(size_t)n * D + k];
        p1 += hv * a1[k];
        p2 += hv * a2[k];
    }
    s1[threadIdx.x] = p1; s2[threadIdx.x] = p2;
    __syncthreads();
    for (int s = 128; s > 0; s >>= 1) {
        if (threadIdx.x < s) { s1[threadIdx.x] += s1[threadIdx.x + s]; s2[threadIdx.x] += s2[threadIdx.x + s]; }
        __syncthreads();
    }
    if (threadIdx.x == 0) { o1[n] = s1[0]; o2[n] = s2[0]; }
}

// GAT aggregation; graph = complete cliques of size `group` with self loops.
__global__ void gat_agg(const float* __restrict__ h, const float* __restrict__ as,
                        const float* __restrict__ ad, const float* __restrict__ bias,
                        float* __restrict__ out, int group)
{
    int n = blockIdx.x;
    int base = (n / group) * group;
    __shared__ float alpha[32];
    if (threadIdx.x == 0) {
        float e[32];
        float mx = -1e30f;
        for (int s = 0; s < group; s++) {
            float x = as[base + s] + ad[n];
            x = (x > 0.f) ? x : 0.2f * x;      // leaky relu 0.2
            e[s] = x;
            mx = fmaxf(mx, x);
        }
        float se = 0.f;
        for (int s = 0; s < group; s++) { e[s] = expf(e[s] - mx); se += e[s]; }
        for (int s = 0; s < group; s++) alpha[s] = e[s] / se;
    }
    __syncthreads();
    for (int dd = threadIdx.x; dd < HD; dd += 256) {
        float acc = 0.f;
        for (int s = 0; s < group; s++)
            acc += alpha[s] * h[(size_t)(base + s) * HD + dd];
        out[(size_t)n * HD + dd] = acc + bias[dd];
    }
}

// fusion concat: [v | cat(bcast) | inner]
__global__ void build_fusion(const float* __restrict__ v, const float* __restrict__ catv,
                             const float* __restrict__ inner, float* __restrict__ fin)
{
    int idx = blockIdx.x * 256 + threadIdx.x;
    if (idx >= NB * H3) return;
    int n = idx / H3, k = idx - n * H3;
    float val;
    if (k < HD)            val = v[(size_t)n * HD + k];
    else if (k < 2 * HD)   val = catv[(size_t)(n / 20) * HD + (k - HD)];
    else                   val = inner[(size_t)n * HD + (k - 2 * HD)];
    fin[idx] = val;
}

// heads: reg and sigmoid cls
__global__ void heads(const float* __restrict__ f, const float* __restrict__ rw,
                      const float* __restrict__ rb, const float* __restrict__ cw,
                      const float* __restrict__ cb, float* __restrict__ out)
{
    int n = blockIdx.x;
    __shared__ float s1[256], s2[256];
    float p1 = 0.f, p2 = 0.f;
    for (int k = threadIdx.x; k < HD; k += 256) {
        float fv = f[(size_t)n * HD + k];
        p1 += fv * rw[k];
        p2 += fv * cw[k];
    }
    s1[threadIdx.x] = p1; s2[threadIdx.x] = p2;
    __syncthreads();
    for (int s = 128; s > 0; s >>= 1) {
        if (threadIdx.x < s) { s1[threadIdx.x] += s1[threadIdx.x + s]; s2[threadIdx.x] += s2[threadIdx.x + s]; }
        __syncthreads();
    }
    if (threadIdx.x == 0) {
        out[n] = s1[0] + rb[0];
        out[NB + n] = 1.f / (1.f + expf(-(s2[0] + cb[0])));
    }
}

// =================================================================
extern "C" void kernel_launch(void* const* d_in, const int* in_sizes, int n_in,
                              void* d_out, int out_size)
{
    const float* weekly  = (const float*)d_in[0];
    const float* Wih     = (const float*)d_in[1];
    const float* Whh     = (const float*)d_in[2];
    const float* bih     = (const float*)d_in[3];
    const float* bhh     = (const float*)d_in[4];
    const float* encW    = (const float*)d_in[5];
    const float* encB    = (const float*)d_in[6];
    const float* poolW   = (const float*)d_in[7];
    const float* poolB   = (const float*)d_in[8];
    const float* innerW  = (const float*)d_in[9];
    const float* innerAs = (const float*)d_in[10];
    const float* innerAd = (const float*)d_in[11];
    const float* innerB  = (const float*)d_in[12];
    const float* catW    = (const float*)d_in[13];
    const float* catAs   = (const float*)d_in[14];
    const float* catAd   = (const float*)d_in[15];
    const float* catB    = (const float*)d_in[16];
    const float* fusW    = (const float*)d_in[17];
    const float* fusB    = (const float*)d_in[18];
    const float* regW    = (const float*)d_in[19];
    const float* regB    = (const float*)d_in[20];
    const float* clsW    = (const float*)d_in[21];
    const float* clsB    = (const float*)d_in[22];
    float* out = (float*)d_out;

    float *xp, *hs, *v, *hp, *inner, *catv, *hp2, *catg, *as_, *ad_, *as2, *ad2, *fin, *f;
    cudaGetSymbolAddress((void**)&xp,    g_xp);
    cudaGetSymbolAddress((void**)&hs,    g_hs);
    cudaGetSymbolAddress((void**)&v,     g_v);
    cudaGetSymbolAddress((void**)&hp,    g_hp);
    cudaGetSymbolAddress((void**)&inner, g_inner);
    cudaGetSymbolAddress((void**)&catv,  g_catv);
    cudaGetSymbolAddress((void**)&hp2,   g_hp2);
    cudaGetSymbolAddress((void**)&catg,  g_cat);
    cudaGetSymbolAddress((void**)&as_,   g_as);
    cudaGetSymbolAddress((void**)&ad_,   g_ad);
    cudaGetSymbolAddress((void**)&as2,   g_as2);
    cudaGetSymbolAddress((void**)&ad2,   g_ad2);
    cudaGetSymbolAddress((void**)&fin,   g_fin);
    cudaGetSymbolAddress((void**)&f,     g_f);

    // 1) xp = weekly(51200,256) @ Wih^T + bih  -> (51200, 3072)
    {
        dim3 grid(H3 / 128, (NB * TT + 127) / 128);
        gemm_nt<<<grid, 256>>>(weekly, Wih, bih, xp, NB * TT, H3, IND, 0);
    }

    // 2) GRU recurrence: 512 sequential steps
    for (int t = 0; t < TT; t++)
        gru_step<<<128, 256>>>(xp, Whh, bhh, hs, t);

    // 3) enc attention scores w[b] = encW @ hs_b + encB   (reuse xp buffer)
    {
        dim3 grid(HD / 128, TT / 128, NB);
        gemm_nn_batched<<<grid, 256>>>(encW, hs, encB, xp, TT, HD, TT,
                                       (size_t)TT * HD, (size_t)TT * HD);
    }

    // 4) v[b,d] = softmax-over-u weighted sum of hs
    {
        dim3 grid(NB, HD / 256);
        att_reduce<<<grid, 256>>>(xp, hs, v, TT, HD);
    }

    // 5) inner GAT projection  hp = v @ innerW^T
    gemm_nt<<<dim3(HD / 128, 1), 256>>>(v, innerW, nullptr, hp, NB, HD, HD, 0);
    dot2<<<NB, 256>>>(hp, innerAs, innerAd, as_, ad_, HD);
    gat_agg<<<NB, 256>>>(hp, as_, ad_, innerB, inner, 20);

    // 6) pool 20 stocks -> category vectors
    pool_att<<<dim3(5, HD / 256), 256>>>(v, poolW, poolB, catv);

    // 7) category GAT
    gemm_nt<<<dim3(HD / 128, 1), 256>>>(catv, catW, nullptr, hp2, 5, HD, HD, 0);
    dot2<<<5, 256>>>(hp2, catAs, catAd, as2, ad2, HD);
    gat_agg<<<5, 256>>>(hp2, as2, ad2, catB, catg, 5);

    // 8) fusion
    build_fusion<<<(NB * H3 + 255) / 256, 256>>>(v, catg, inner, fin);
    gemm_nt<<<dim3(HD / 128, 1), 256>>>(fin, fusW, fusB, f, NB, HD, H3, 1);

    // 9) heads -> d_out[0:100]=reg, d_out[100:200]=cls
    heads<<<NB, 256>>>(f, regW, regB, clsW, clsB, out);
}

// round 2
// speedup vs baseline: 1.0017x; 1.0017x over previous
#include <cuda_runtime.h>
#include <math.h>
#include <stdint.h>
#include <stddef.h>

// ---------------- problem dims ----------------
#define NB   100      // nodes / batch
#define TT   512      // time steps
#define IND  256      // input dim
#define HD   1024     // hidden
#define H3   3072     // 3*H

// ---------------- scratch (device globals; no allocation allowed) ----------------
__device__ float g_xp[(size_t)NB * TT * H3];     // 629 MB: xp, later reused as attention scores w
__device__ float g_hs[(size_t)NB * TT * HD];     // 210 MB: all hidden states
__device__ float g_v[NB * HD];
__device__ float g_hp[NB * HD];
__device__ float g_inner[NB * HD];
__device__ float g_catv[5 * HD];
__device__ float g_hp2[5 * HD];
__device__ float g_cat[5 * HD];
__device__ float g_as[NB];
__device__ float g_ad[NB];
__device__ float g_as2[8];
__device__ float g_ad2[8];
__device__ float g_fin[NB * H3];
__device__ float g_f[NB * HD];

// =================================================================
// Generic tiled SGEMM:  C[M,N] = A[M,K] @ B[N,K]^T (+ bias[N]) (+relu)
// A row-major MxK, B row-major NxK. 128x128 tile, BK=16, 256 thr, 8x8 micro.
// Requires K % 16 == 0.
// =================================================================
__global__ __launch_bounds__(256) void gemm_nt(
    const float* __restrict__ A, const float* __restrict__ B,
    const float* __restrict__ bias, float* __restrict__ C,
    int M, int N, int K, int act)
{
    __shared__ float As[16][128];
    __shared__ float Bs[16][128];
    int tid = threadIdx.x;
    int tx = tid & 15, ty = tid >> 4;
    int row0 = blockIdx.y * 128, col0 = blockIdx.x * 128;

    float acc[8][8];
#pragma unroll
    for (int i = 0; i < 8; i++)
#pragma unroll
        for (int j = 0; j < 8; j++) acc[i][j] = 0.f;

    int lr = tid >> 2;   // 0..63
    int lc = tid & 3;    // k-offset group

    for (int k0 = 0; k0 < K; k0 += 16) {
#pragma unroll
        for (int p = 0; p < 2; p++) {
            int r = lr + p * 64;
            int gr = row0 + r;
            float4 v = make_float4(0.f, 0.f, 0.f, 0.f);
            if (gr < M) v = *(const float4*)(A + (size_t)gr * K + k0 + lc * 4);
            As[lc * 4 + 0][r] = v.x; As[lc * 4 + 1][r] = v.y;
            As[lc * 4 + 2][r] = v.z; As[lc * 4 + 3][r] = v.w;
        }
#pragma unroll
        for (int p = 0; p < 2; p++) {
            int r = lr + p * 64;
            int gc = col0 + r;
            float4 v = make_float4(0.f, 0.f, 0.f, 0.f);
            if (gc < N) v = *(const float4*)(B + (size_t)gc * K + k0 + lc * 4);
            Bs[lc * 4 + 0][r] = v.x; Bs[lc * 4 + 1][r] = v.y;
            Bs[lc * 4 + 2][r] = v.z; Bs[lc * 4 + 3][r] = v.w;
        }
        __syncthreads();
#pragma unroll
        for (int kk = 0; kk < 16; kk++) {
            float a[8], b[8];
            *(float4*)&a[0] = *(const float4*)&As[kk][ty * 8];
            *(float4*)&a[4] = *(const float4*)&As[kk][ty * 8 + 4];
            *(float4*)&b[0] = *(const float4*)&Bs[kk][tx * 8];
            *(float4*)&b[4] = *(const float4*)&Bs[kk][tx * 8 + 4];
#pragma unroll
            for (int i = 0; i < 8; i++)
#pragma unroll
                for (int j = 0; j < 8; j++) acc[i][j] += a[i] * b[j];
        }
        __syncthreads();
    }

#pragma unroll
    for (int i = 0; i < 8; i++) {
        int gm = row0 + ty * 8 + i;
        if (gm >= M) continue;
#pragma unroll
        for (int j = 0; j < 8; j++) {
            int gn = col0 + tx * 8 + j;
            if (gn >= N) continue;
            float v = acc[i][j];
            if (bias) v += bias[gn];
            if (act == 1) v = fmaxf(v, 0.f);
            C[(size_t)gm * N + gn] = v;
        }
    }
}

// =================================================================
// Batched NN GEMM for enc attention:
//   C_b[u,d] = sum_t A[u,t] * B_b[t,d]  + rowbias[u]
// A: MxK shared across batch; B_b = Bbase + z*strideB (KxN); C likewise.
// M,N multiples of 128; K multiple of 16.
// =================================================================
__global__ __launch_bounds__(256) void gemm_nn_batched(
    const float* __restrict__ A, const float* __restrict__ Bbase,
    const float* __restrict__ rowbias, float* __restrict__ Cbase,
    int M, int N, int K, size_t strideB, size_t strideC)
{
    const float* B = Bbase + (size_t)blockIdx.z * strideB;
    float* C = Cbase + (size_t)blockIdx.z * strideC;
    __shared__ float As[16][128];
    __shared__ float Bs[16][128];
    int tid = threadIdx.x;
    int tx = tid & 15, ty = tid >> 4;
    int row0 = blockIdx.y * 128, col0 = blockIdx.x * 128;

    float acc[8][8];
#pragma unroll
    for (int i = 0; i < 8; i++)
#pragma unroll
        for (int j = 0; j < 8; j++) acc[i][j] = 0.f;

    int lr = tid >> 2;
    int lc = tid & 3;
    int br = tid >> 5;       // 0..7
    int bc = tid & 31;       // 0..31

    for (int k0 = 0; k0 < K; k0 += 16) {
#pragma unroll
        for (int p = 0; p < 2; p++) {
            int r = lr + p * 64;
            int gr = row0 + r;
            float4 v = make_float4(0.f, 0.f, 0.f, 0.f);
            if (gr < M) v = *(const float4*)(A + (size_t)gr * K + k0 + lc * 4);
            As[lc * 4 + 0][r] = v.x; As[lc * 4 + 1][r] = v.y;
            As[lc * 4 + 2][r] = v.z; As[lc * 4 + 3][r] = v.w;
        }
#pragma unroll
        for (int p = 0; p < 2; p++) {
            int k = br + p * 8;
            float4 v = *(const float4*)(B + (size_t)(k0 + k) * N + col0 + bc * 4);
            *(float4*)&Bs[k][bc * 4] = v;
        }
        __syncthreads();
#pragma unroll
        for (int kk = 0; kk < 16; kk++) {
            float a[8], b[8];
            *(float4*)&a[0] = *(const float4*)&As[kk][ty * 8];
            *(float4*)&a[4] = *(const float4*)&As[kk][ty * 8 + 4];
            *(float4*)&b[0] = *(const float4*)&Bs[kk][tx * 8];
            *(float4*)&b[4] = *(const float4*)&Bs[kk][tx * 8 + 4];
#pragma unroll
            for (int i = 0; i < 8; i++)
#pragma unroll
                for (int j = 0; j < 8; j++) acc[i][j] += a[i] * b[j];
        }
        __syncthreads();
    }

#pragma unroll
    for (int i = 0; i < 8; i++) {
        int gm = row0 + ty * 8 + i;
        float rb = rowbias[gm];
#pragma unroll
        for (int j = 0; j < 8; j++) {
            int gn = col0 + tx * 8 + j;
            C[(size_t)gm * N + gn] = acc[i][j] + rb;
        }
    }
}

// =================================================================
// One GRU time step. grid=128 blocks x 256 thr. warp w owns column
// c = blockIdx.x*8 + w; keeps Whh rows {c, H+c, 2H+c} in registers.
// Reads hs[:,t-1,:], xp[:,t,:], writes hs[:,t,:].
// =================================================================
__global__ __launch_bounds__(256) void gru_step(
    const float* __restrict__ xp, const float* __restrict__ Whh,
    const float* __restrict__ bhh, float* __restrict__ hs, int t)
{
    int warp = threadIdx.x >> 5;
    int lane = threadIdx.x & 31;
    int c = blockIdx.x * 8 + warp;       // 0..1023
    int ks = lane * 32;                  // this lane's contiguous K-slice

    float4 w0[8], w1[8], w2[8];
    {
        const float4* p0 = (const float4*)(Whh + (size_t)(0 * HD + c) * HD + ks);
        const float4* p1 = (const float4*)(Whh + (size_t)(1 * HD + c) * HD + ks);
        const float4* p2 = (const float4*)(Whh + (size_t)(2 * HD + c) * HD + ks);
#pragma unroll
        for (int j = 0; j < 8; j++) { w0[j] = p0[j]; w1[j] = p1[j]; w2[j] = p2[j]; }
    }
    float b0 = bhh[c], b1 = bhh[HD + c], b2 = bhh[2 * HD + c];

    for (int b = 0; b < NB; b++) {
        float a0 = 0.f, a1 = 0.f, a2 = 0.f;
        const float* hrow = hs + ((size_t)b * TT + (t - 1)) * HD;
        if (t > 0) {
            const float4* hp4 = (const float4*)(hrow + ks);
#pragma unroll
            for (int j = 0; j < 8; j++) {
                float4 h4 = hp4[j];
                a0 += h4.x * w0[j].x + h4.y * w0[j].y + h4.z * w0[j].z + h4.w * w0[j].w;
                a1 += h4.x * w1[j].x + h4.y * w1[j].y + h4.z * w1[j].z + h4.w * w1[j].w;
                a2 += h4.x * w2[j].x + h4.y * w2[j].y + h4.z * w2[j].z + h4.w * w2[j].w;
            }
        }
#pragma unroll
        for (int off = 16; off > 0; off >>= 1) {
            a0 += __shfl_down_sync(0xffffffffu, a0, off);
            a1 += __shfl_down_sync(0xffffffffu, a1, off);
            a2 += __shfl_down_sync(0xffffffffu, a2, off);
        }
        if (lane == 0) {
            size_t xi = ((size_t)b * TT + t) * H3;
            float xr = xp[xi + c];
            float xz = xp[xi + HD + c];
            float xn = xp[xi + 2 * HD + c];
            float r = 1.f / (1.f + expf(-(xr + a0 + b0)));
            float z = 1.f / (1.f + expf(-(xz + a1 + b1)));
            float n = tanhf(xn + r * (a2 + b2));
            float hold = (t > 0) ? hrow[c] : 0.f;
            hs[((size_t)b * TT + t) * HD + c] = (1.f - z) * n + z * hold;
        }
    }
}

// =================================================================
// Attention reduce over time:  out[b,d] = sum_u softmax_u(w[b,u,d]) * x[b,u,d]
// =================================================================
__global__ void att_reduce(const float* __restrict__ w, const float* __restrict__ x,
                           float* __restrict__ out, int U, int D)
{
    int b = blockIdx.x;
    int d = blockIdx.y * blockDim.x + threadIdx.x;
    const float* wb = w + (size_t)b * U * D;
    const float* xb = x + (size_t)b * U * D;
    float mx = -1e30f;
    for (int u = 0; u < U; u++) mx = fmaxf(mx, wb[(size_t)u * D + d]);
    float se = 0.f, sv = 0.f;
    for (int u = 0; u < U; u++) {
        float e = expf(wb[(size_t)u * D + d] - mx);
        se += e;
        sv += e * xb[(size_t)u * D + d];
    }
    out[(size_t)b * D + d] = sv / se;
}

// =================================================================
// Pool attention: 20 stocks -> 1 category vector (per category c)
// =================================================================
__global__ void pool_att(const float* __restrict__ v, const float* __restrict__ pW,
                         const float* __restrict__ pb, float* __restrict__ out)
{
    int c = blockIdx.x;
    int d = blockIdx.y * 256 + threadIdx.x;
    __shared__ float sW[400];
    __shared__ float sb[20];
    for (int i = threadIdx.x; i < 400; i += 256) sW[i] = pW[i];
    if (threadIdx.x < 20) sb[threadIdx.x] = pb[threadIdx.x];
    __syncthreads();

    float xv[20];
#pragma unroll
    for (int t = 0; t < 20; t++) xv[t] = v[(size_t)(c * 20 + t) * HD + d];
    float wv[20];
    float mx = -1e30f;
#pragma unroll
    for (int u = 0; u < 20; u++) {
        float s = sb[u];
#pragma unroll
        for (int t = 0; t < 20; t++) s += xv[t] * sW[u * 20 + t];
        wv[u] = s;
        mx = fmaxf(mx, s);
    }
    float se = 0.f, sv = 0.f;
#pragma unroll
    for (int u = 0; u < 20; u++) {
        float e = expf(wv[u] - mx);
        se += e;
        sv += e * xv[u];
    }
    out[(size_t)c * HD + d] = sv / se;
}

// two dot products per node: as[n]=h[n,:].a1, ad[n]=h[n,:].a2
__global__ void dot2(const float* __restrict__ h, const float* __restrict__ a1,
                     const float* __restrict__ a2, float* __restrict__ o1,
                     float* __restrict__ o2, int D)
{
    int n = blockIdx.x;
    __shared__ float s1[256], s2[256];
    float p1 = 0.f, p2 = 0.f;
    for (int k = threadIdx.x; k < D; k += 256) {
        float hv = h[(size_t)n * D + k];
        p1 += hv * a1[k];
        p2 += hv * a2[k];
    }
    s1[threadIdx.x] = p1; s2[threadIdx.x] = p2;
    __syncthreads();
    for (int s = 128; s > 0; s >>= 1) {
        if (threadIdx.x < s) { s1[threadIdx.x] += s1[threadIdx.x + s]; s2[threadIdx.x] += s2[threadIdx.x + s]; }
        __syncthreads();
    }
    if (threadIdx.x == 0) { o1[n] = s1[0]; o2[n] = s2[0]; }
}

// GAT aggregation; graph = complete cliques of size `group` with self loops.
__global__ void gat_agg(const float* __restrict__ h, const float* __restrict__ as,
                        const float* __restrict__ ad, const float* __restrict__ bias,
                        float* __restrict__ out, int group)
{
    int n = blockIdx.x;
    int base = (n / group) * group;
    __shared__ float alpha[32];
    if (threadIdx.x == 0) {
        float e[32];
        float mx = -1e30f;
        for (int s = 0; s < group; s++) {
            float x = as[base + s] + ad[n];
            x = (x > 0.f) ? x : 0.2f * x;      // leaky relu 0.2
            e[s] = x;
            mx = fmaxf(mx, x);
        }
        float se = 0.f;
        for (int s = 0; s < group; s++) { e[s] = expf(e[s] - mx); se += e[s]; }
        for (int s = 0; s < group; s++) alpha[s] = e[s] / se;
    }
    __syncthreads();
    for (int dd = threadIdx.x; dd < HD; dd += 256) {
        float acc = 0.f;
        for (int s = 0; s < group; s++)
            acc += alpha[s] * h[(size_t)(base + s) * HD + dd];
        out[(size_t)n * HD + dd] = acc + bias[dd];
    }
}

// fusion concat: [v | cat(bcast) | inner]
__global__ void build_fusion(const float* __restrict__ v, const float* __restrict__ catv,
                             const float* __restrict__ inner, float* __restrict__ fin)
{
    int idx = blockIdx.x * 256 + threadIdx.x;
    if (idx >= NB * H3) return;
    int n = idx / H3, k = idx - n * H3;
    float val;
    if (k < HD)            val = v[(size_t)n * HD + k];
    else if (k < 2 * HD)   val = catv[(size_t)(n / 20) * HD + (k - HD)];
    else                   val = inner[(size_t)n * HD + (k - 2 * HD)];
    fin[idx] = val;
}

// heads: reg and sigmoid cls
__global__ void heads(const float* __restrict__ f, const float* __restrict__ rw,
                      const float* __restrict__ rb, const float* __restrict__ cw,
                      const float* __restrict__ cb, float* __restrict__ out)
{
    int n = blockIdx.x;
    __shared__ float s1[256], s2[256];
    float p1 = 0.f, p2 = 0.f;
    for (int k = threadIdx.x; k < HD; k += 256) {
        float fv = f[(size_t)n * HD + k];
        p1 += fv * rw[k];
        p2 += fv * cw[k];
    }
    s1[threadIdx.x] = p1; s2[threadIdx.x] = p2;
    __syncthreads();
    for (int s = 128; s > 0; s >>= 1) {
        if (threadIdx.x < s) { s1[threadIdx.x] += s1[threadIdx.x + s]; s2[threadIdx.x] += s2[threadIdx.x + s]; }
        __syncthreads();
    }
    if (threadIdx.x == 0) {
        out[n] = s1[0] + rb[0];
        out[NB + n] = 1.f / (1.f + expf(-(s2[0] + cb[0])));
    }
}

// =================================================================
extern "C" void kernel_launch(void* const* d_in, const int* in_sizes, int n_in,
                              void* d_out, int out_size)
{
    const float* weekly  = (const float*)d_in[0];
    const float* Wih     = (const float*)d_in[1];
    const float* Whh     = (const float*)d_in[2];
    const float* bih     = (const float*)d_in[3];
    const float* bhh     = (const float*)d_in[4];
    const float* encW    = (const float*)d_in[5];
    const float* encB    = (const float*)d_in[6];
    const float* poolW   = (const float*)d_in[7];
    const float* poolB   = (const float*)d_in[8];
    const float* innerW  = (const float*)d_in[9];
    const float* innerAs = (const float*)d_in[10];
    const float* innerAd = (const float*)d_in[11];
    const float* innerB  = (const float*)d_in[12];
    const float* catW    = (const float*)d_in[13];
    const float* catAs   = (const float*)d_in[14];
    const float* catAd   = (const float*)d_in[15];
    const float* catB    = (const float*)d_in[16];
    const float* fusW    = (const float*)d_in[17];
    const float* fusB    = (const float*)d_in[18];
    const float* regW    = (const float*)d_in[19];
    const float* regB    = (const float*)d_in[20];
    const float* clsW    = (const float*)d_in[21];
    const float* clsB    = (const float*)d_in[22];
    float* out = (float*)d_out;

    float *xp, *hs, *v, *hp, *inner, *catv, *hp2, *catg, *as_, *ad_, *as2, *ad2, *fin, *f;
    cudaGetSymbolAddress((void**)&xp,    g_xp);
    cudaGetSymbolAddress((void**)&hs,    g_hs);
    cudaGetSymbolAddress((void**)&v,     g_v);
    cudaGetSymbolAddress((void**)&hp,    g_hp);
    cudaGetSymbolAddress((void**)&inner, g_inner);
    cudaGetSymbolAddress((void**)&catv,  g_catv);
    cudaGetSymbolAddress((void**)&hp2,   g_hp2);
    cudaGetSymbolAddress((void**)&catg,  g_cat);
    cudaGetSymbolAddress((void**)&as_,   g_as);
    cudaGetSymbolAddress((void**)&ad_,   g_ad);
    cudaGetSymbolAddress((void**)&as2,   g_as2);
    cudaGetSymbolAddress((void**)&ad2,   g_ad2);
    cudaGetSymbolAddress((void**)&fin,   g_fin);
    cudaGetSymbolAddress((void**)&f,     g_f);

    // 1) xp = weekly(51200,256) @ Wih^T + bih  -> (51200, 3072)
    {
        dim3 grid(H3 / 128, (NB * TT + 127) / 128);
        gemm_nt<<<grid, 256>>>(weekly, Wih, bih, xp, NB * TT, H3, IND, 0);
    }

    // 2) GRU recurrence: 512 sequential steps
    for (int t = 0; t < TT; t++)
        gru_step<<<128, 256>>>(xp, Whh, bhh, hs, t);

    // 3) enc attention scores w[b] = encW @ hs_b + encB   (reuse xp buffer)
    {
        dim3 grid(HD / 128, TT / 128, NB);
        gemm_nn_batched<<<grid, 256>>>(encW, hs, encB, xp, TT, HD, TT,
                                       (size_t)TT * HD, (size_t)TT * HD);
    }

    // 4) v[b,d] = softmax-over-u weighted sum of hs
    {
        dim3 grid(NB, HD / 256);
        att_reduce<<<grid, 256>>>(xp, hs, v, TT, HD);
    }

    // 5) inner GAT projection  hp = v @ innerW^T
    gemm_nt<<<dim3(HD / 128, 1), 256>>>(v, innerW, nullptr, hp, NB, HD, HD, 0);
    dot2<<<NB, 256>>>(hp, innerAs, innerAd, as_, ad_, HD);
    gat_agg<<<NB, 256>>>(hp, as_, ad_, innerB, inner, 20);

    // 6) pool 20 stocks -> category vectors
    pool_att<<<dim3(5, HD / 256), 256>>>(v, poolW, poolB, catv);

    // 7) category GAT
    gemm_nt<<<dim3(HD / 128, 1), 256>>>(catv, catW, nullptr, hp2, 5, HD, HD, 0);
    dot2<<<5, 256>>>(hp2, catAs, catAd, as2, ad2, HD);
    gat_agg<<<5, 256>>>(hp2, as2, ad2, catB, catg, 5);

    // 8) fusion
    build_fusion<<<(NB * H3 + 255) / 256, 256>>>(v, catg, inner, fin);
    gemm_nt<<<dim3(HD / 128, 1), 256>>>(fin, fusW, fusB, f, NB, HD, H3, 1);

    // 9) heads -> d_out[0:100]=reg, d_out[100:200]=cls
    heads<<<NB, 256>>>(f, regW, regB, clsW, clsB, out);
}

// round 3
// speedup vs baseline: 3.6472x; 3.6410x over previous
#include <cuda_runtime.h>
#include <math.h>
#include <stdint.h>
#include <stddef.h>

typedef unsigned long long u64;

#define NB   100
#define TT   512
#define IND  256
#define HD   1024
#define H3   3072
#define NDB  (HD * NB)   // 102400

// ---------------- scratch ----------------
__device__ float g_xp [(size_t)NB * TT * H3];   // xp [b][t][g]; later reused as S [u][(d,b)]
__device__ float g_hst[(size_t)TT * HD * NB];   // h states [t][d][b]
__device__ float g_vt  [NDB];
__device__ float g_hpt [NDB];
__device__ float g_innert[NDB];
__device__ float g_catv8[HD * 8];
__device__ float g_hp2t [HD * 8];
__device__ float g_catot[HD * 5];
__device__ float g_as[NB];
__device__ float g_ad[NB];
__device__ float g_as2[8];
__device__ float g_ad2[8];
__device__ float g_fint[H3 * NB];
__device__ float g_ft  [HD * NB];
__device__ unsigned g_cnt;
__device__ unsigned g_gen;

// ---------------- f32x2 helpers ----------------
__device__ __forceinline__ u64 bcast2(float x) {
    u64 r; unsigned u = __float_as_uint(x);
    asm("mov.b64 %0, {%1, %1};" : "=l"(r) : "r"(u));
    return r;
}
__device__ __forceinline__ void fma2(u64& d, u64 a, u64 b) {
    asm("fma.rn.f32x2 %0, %1, %2, %0;" : "+l"(d) : "l"(a), "l"(b));
}
__device__ __forceinline__ float2 unpk(u64 v) {
    unsigned lo, hi;
    asm("mov.b64 {%0, %1}, %2;" : "=r"(lo), "=r"(hi) : "l"(v));
    return make_float2(__uint_as_float(lo), __uint_as_float(hi));
}
__device__ __forceinline__ float sigf(float x) { return 1.f / (1.f + expf(-x)); }

// =================================================================
// SGEMM NT: C[M,N] = A[M,K] @ B[N,K]^T + colbias[N]
// =================================================================
__global__ __launch_bounds__(256) void gemm_nt(
    const float* __restrict__ A, const float* __restrict__ B,
    const float* __restrict__ colbias, float* __restrict__ C,
    int M, int N, int K, int act)
{
    __shared__ float As[16][128];
    __shared__ float Bs[16][128];
    int tid = threadIdx.x;
    int tx = tid & 15, ty = tid >> 4;
    int row0 = blockIdx.y * 128, col0 = blockIdx.x * 128;

    u64 acc[8][4];
#pragma unroll
    for (int i = 0; i < 8; i++)
#pragma unroll
        for (int j = 0; j < 4; j++) acc[i][j] = 0ull;

    int lr = tid >> 2, lc = tid & 3;
    for (int k0 = 0; k0 < K; k0 += 16) {
#pragma unroll
        for (int p = 0; p < 2; p++) {
            int r = lr + p * 64, gr = row0 + r;
            float4 v = make_float4(0.f, 0.f, 0.f, 0.f);
            if (gr < M) v = *(const float4*)(A + (size_t)gr * K + k0 + lc * 4);
            As[lc*4+0][r] = v.x; As[lc*4+1][r] = v.y; As[lc*4+2][r] = v.z; As[lc*4+3][r] = v.w;
        }
#pragma unroll
        for (int p = 0; p < 2; p++) {
            int r = lr + p * 64, gc = col0 + r;
            float4 v = make_float4(0.f, 0.f, 0.f, 0.f);
            if (gc < N) v = *(const float4*)(B + (size_t)gc * K + k0 + lc * 4);
            Bs[lc*4+0][r] = v.x; Bs[lc*4+1][r] = v.y; Bs[lc*4+2][r] = v.z; Bs[lc*4+3][r] = v.w;
        }
        __syncthreads();
#pragma unroll
        for (int kk = 0; kk < 16; kk++) {
            float a[8];
            *(float4*)&a[0] = *(const float4*)&As[kk][ty * 8];
            *(float4*)&a[4] = *(const float4*)&As[kk][ty * 8 + 4];
            u64 b4[4];
#pragma unroll
            for (int j = 0; j < 4; j++) b4[j] = *(const u64*)&Bs[kk][tx * 8 + 2 * j];
#pragma unroll
            for (int i = 0; i < 8; i++) {
                u64 ai = bcast2(a[i]);
#pragma unroll
                for (int j = 0; j < 4; j++) fma2(acc[i][j], ai, b4[j]);
            }
        }
        __syncthreads();
    }
#pragma unroll
    for (int i = 0; i < 8; i++) {
        int gm = row0 + ty * 8 + i;
        if (gm >= M) continue;
#pragma unroll
        for (int j = 0; j < 4; j++) {
            float2 c2 = unpk(acc[i][j]);
            int gn = col0 + tx * 8 + 2 * j;
            float v0 = c2.x, v1 = c2.y;
            if (colbias) { v0 += colbias[gn]; v1 += colbias[gn + 1]; }
            if (act == 1) { v0 = fmaxf(v0, 0.f); v1 = fmaxf(v1, 0.f); }
            if (gn < N)     C[(size_t)gm * N + gn]     = v0;
            if (gn + 1 < N) C[(size_t)gm * N + gn + 1] = v1;
        }
    }
}

// =================================================================
// SGEMM NN: C[M,N] = A[M,K] @ B[K,N] (+ rowbias[M]) (+relu). N%4==0.
// =================================================================
__global__ __launch_bounds__(256) void gemm_nn(
    const float* __restrict__ A, const float* __restrict__ B,
    const float* __restrict__ rowbias, float* __restrict__ C,
    int M, int N, int K, int act)
{
    __shared__ float As[16][128];
    __shared__ float Bs[16][128];
    int tid = threadIdx.x;
    int tx = tid & 15, ty = tid >> 4;
    int row0 = blockIdx.y * 128, col0 = blockIdx.x * 128;

    u64 acc[8][4];
#pragma unroll
    for (int i = 0; i < 8; i++)
#pragma unroll
        for (int j = 0; j < 4; j++) acc[i][j] = 0ull;

    int lr = tid >> 2, lc = tid & 3;
    int br = tid >> 5, bc = tid & 31;
    for (int k0 = 0; k0 < K; k0 += 16) {
#pragma unroll
        for (int p = 0; p < 2; p++) {
            int r = lr + p * 64, gr = row0 + r;
            float4 v = make_float4(0.f, 0.f, 0.f, 0.f);
            if (gr < M) v = *(const float4*)(A + (size_t)gr * K + k0 + lc * 4);
            As[lc*4+0][r] = v.x; As[lc*4+1][r] = v.y; As[lc*4+2][r] = v.z; As[lc*4+3][r] = v.w;
        }
#pragma unroll
        for (int p = 0; p < 2; p++) {
            int k = br + p * 8;
            int gc = col0 + bc * 4;
            float4 v = make_float4(0.f, 0.f, 0.f, 0.f);
            if (gc < N) v = *(const float4*)(B + (size_t)(k0 + k) * N + gc);
            *(float4*)&Bs[k][bc * 4] = v;
        }
        __syncthreads();
#pragma unroll
        for (int kk = 0; kk < 16; kk++) {
            float a[8];
            *(float4*)&a[0] = *(const float4*)&As[kk][ty * 8];
            *(float4*)&a[4] = *(const float4*)&As[kk][ty * 8 + 4];
            u64 b4[4];
#pragma unroll
            for (int j = 0; j < 4; j++) b4[j] = *(const u64*)&Bs[kk][tx * 8 + 2 * j];
#pragma unroll
            for (int i = 0; i < 8; i++) {
                u64 ai = bcast2(a[i]);
#pragma unroll
                for (int j = 0; j < 4; j++) fma2(acc[i][j], ai, b4[j]);
            }
        }
        __syncthreads();
    }
#pragma unroll
    for (int i = 0; i < 8; i++) {
        int gm = row0 + ty * 8 + i;
        if (gm >= M) continue;
        float rb = rowbias ? rowbias[gm] : 0.f;
#pragma unroll
        for (int j = 0; j < 4; j++) {
            float2 c2 = unpk(acc[i][j]);
            int gn = col0 + tx * 8 + 2 * j;
            float v0 = c2.x + rb, v1 = c2.y + rb;
            if (act == 1) { v0 = fmaxf(v0, 0.f); v1 = fmaxf(v1, 0.f); }
            if (gn < N)     C[(size_t)gm * N + gn]     = v0;
            if (gn + 1 < N) C[(size_t)gm * N + gn + 1] = v1;
        }
    }
}

// =================================================================
// Persistent GRU. 128 blocks x 200 threads, all co-resident.
// Block owns 8 columns; Whh slice in smem duplicated as f32x2 (196KB).
// Thread = 2 columns x 2 batches. Grid barrier between steps.
// =================================================================
__device__ __forceinline__ void gridbar()
{
    __threadfence();
    __syncthreads();
    if (threadIdx.x == 0) {
        volatile unsigned* vg = &g_gen;
        unsigned target = *vg + 1;
        if (atomicAdd(&g_cnt, 1) == gridDim.x - 1) {
            g_cnt = 0;
            __threadfence();
            atomicAdd(&g_gen, 1);
        } else {
            while ((int)(*vg - target) < 0) { __nanosleep(64); }
        }
        __threadfence();
    }
    __syncthreads();
}

__device__ __forceinline__ float gru_out(float xr, float xz, float xn,
                                         float ar, float az, float an,
                                         float br, float bz, float bn, float hold)
{
    float r = sigf(xr + ar + br);
    float z = sigf(xz + az + bz);
    float n = tanhf(xn + r * (an + bn));
    return (1.f - z) * n + z * hold;
}

__global__ __launch_bounds__(200, 1) void gru_persist(
    const float* __restrict__ xp, const float* __restrict__ Whh,
    const float* __restrict__ bhh, float* __restrict__ hst)
{
    extern __shared__ u64 swd[];   // [8 cols][3 gates][1024] duplicated pairs
    int tid = threadIdx.x;
    int colL = tid / 50;           // 0..3
    int bp   = tid % 50;           // batches 2bp, 2bp+1
    int c0 = blockIdx.x * 8 + colL * 2;
    int c1 = c0 + 1;

    for (int i = tid; i < 8 * 3 * 256; i += 200) {
        int cl = i / 768, rem = i % 768, g = rem / 256, k4 = rem % 256;
        float4 w = *(const float4*)(Whh + ((size_t)g * HD + blockIdx.x * 8 + cl) * HD + k4 * 4);
        u64* dst = &swd[(size_t)(cl * 3 + g) * 1024 + k4 * 4];
        dst[0] = bcast2(w.x); dst[1] = bcast2(w.y); dst[2] = bcast2(w.z); dst[3] = bcast2(w.w);
    }
    float br0 = bhh[c0], bz0 = bhh[HD + c0], bn0 = bhh[2*HD + c0];
    float br1 = bhh[c1], bz1 = bhh[HD + c1], bn1 = bhh[2*HD + c1];
    __syncthreads();

    const u64* ws[6];
    ws[0] = &swd[(size_t)((colL*2+0)*3 + 0) * 1024];
    ws[1] = &swd[(size_t)((colL*2+0)*3 + 1) * 1024];
    ws[2] = &swd[(size_t)((colL*2+0)*3 + 2) * 1024];
    ws[3] = &swd[(size_t)((colL*2+1)*3 + 0) * 1024];
    ws[4] = &swd[(size_t)((colL*2+1)*3 + 1) * 1024];
    ws[5] = &swd[(size_t)((colL*2+1)*3 + 2) * 1024];

    for (int t = 0; t < TT; t++) {
        u64 acc[6] = {0, 0, 0, 0, 0, 0};
        float2 hold0 = make_float2(0.f, 0.f), hold1 = make_float2(0.f, 0.f);
        if (t > 0) {
            const float* hp = hst + (size_t)(t - 1) * NDB + 2 * bp;
            hold0 = *(const float2*)(hp + (size_t)c0 * NB);
            hold1 = *(const float2*)(hp + (size_t)c1 * NB);
#pragma unroll 2
            for (int k = 0; k < HD; k += 4) {
                u64 h0 = *(const u64*)(hp + (size_t)(k + 0) * NB);
                u64 h1 = *(const u64*)(hp + (size_t)(k + 1) * NB);
                u64 h2 = *(const u64*)(hp + (size_t)(k + 2) * NB);
                u64 h3 = *(const u64*)(hp + (size_t)(k + 3) * NB);
#pragma unroll
                for (int s = 0; s < 6; s++) {
                    ulonglong2 wa = *(const ulonglong2*)(ws[s] + k);
                    ulonglong2 wb = *(const ulonglong2*)(ws[s] + k + 2);
                    fma2(acc[s], wa.x, h0); fma2(acc[s], wa.y, h1);
                    fma2(acc[s], wb.x, h2); fma2(acc[s], wb.y, h3);
                }
            }
        }
        float2 ar0 = unpk(acc[0]), az0 = unpk(acc[1]), an0 = unpk(acc[2]);
        float2 ar1 = unpk(acc[3]), az1 = unpk(acc[4]), an1 = unpk(acc[5]);

        size_t x0 = ((size_t)(2 * bp) * TT + t) * H3;
        size_t x1 = ((size_t)(2 * bp + 1) * TT + t) * H3;

        float h00 = gru_out(xp[x0 + c0], xp[x0 + HD + c0], xp[x0 + 2*HD + c0],
                            ar0.x, az0.x, an0.x, br0, bz0, bn0, hold0.x);
        float h01 = gru_out(xp[x1 + c0], xp[x1 + HD + c0], xp[x1 + 2*HD + c0],
                            ar0.y, az0.y, an0.y, br0, bz0, bn0, hold0.y);
        float h10 = gru_out(xp[x0 + c1], xp[x0 + HD + c1], xp[x0 + 2*HD + c1],
                            ar1.x, az1.x, an1.x, br1, bz1, bn1, hold1.x);
        float h11 = gru_out(xp[x1 + c1], xp[x1 + HD + c1], xp[x1 + 2*HD + c1],
                            ar1.y, az1.y, an1.y, br1, bz1, bn1, hold1.y);

        float* ho = hst + (size_t)t * NDB + 2 * bp;
        *(float2*)(ho + (size_t)c0 * NB) = make_float2(h00, h01);
        *(float2*)(ho + (size_t)c1 * NB) = make_float2(h10, h11);

        gridbar();
    }
}

// =================================================================
// flat time softmax reduce: vt[j] = sum_u softmax_u(S[u,j]) * H[u,j]
// =================================================================
__global__ void att_reduce_flat(const float* __restrict__ S,
                                const float* __restrict__ H,
                                float* __restrict__ vt)
{
    int j = blockIdx.x * 256 + threadIdx.x;
    float mx = -1e30f;
#pragma unroll 4
    for (int u = 0; u < TT; u++) mx = fmaxf(mx, S[(size_t)u * NDB + j]);
    float se = 0.f, sv = 0.f;
#pragma unroll 4
    for (int u = 0; u < TT; u++) {
        float e = expf(S[(size_t)u * NDB + j] - mx);
        se += e;
        sv += e * H[(size_t)u * NDB + j];
    }
    vt[j] = sv / se;
}

// pool attention on vt[d][b] -> catv8[d*8 + c], c in 0..4 (5..7 zero pad)
__global__ void pool_att_t(const float* __restrict__ vt, const float* __restrict__ pW,
                           const float* __restrict__ pb, float* __restrict__ catv8)
{
    int c = blockIdx.x;
    int d = blockIdx.y * 256 + threadIdx.x;
    if (c >= 5) { catv8[(size_t)d * 8 + c] = 0.f; return; }
    __shared__ float sW[400];
    __shared__ float sb[20];
    for (int i = threadIdx.x; i < 400; i += 256) sW[i] = pW[i];
    if (threadIdx.x < 20) sb[threadIdx.x] = pb[threadIdx.x];
    __syncthreads();

    float xv[20];
#pragma unroll
    for (int s = 0; s < 20; s++) xv[s] = vt[(size_t)d * NB + c * 20 + s];
    float wv[20]; float mx = -1e30f;
#pragma unroll
    for (int u = 0; u < 20; u++) {
        float s = sb[u];
#pragma unroll
        for (int t2 = 0; t2 < 20; t2++) s += xv[t2] * sW[u * 20 + t2];
        wv[u] = s; mx = fmaxf(mx, s);
    }
    float se = 0.f, sv = 0.f;
#pragma unroll
    for (int u = 0; u < 20; u++) {
        float e = expf(wv[u] - mx);
        se += e; sv += e * xv[u];
    }
    catv8[(size_t)d * 8 + c] = sv / se;
}

// two dots per node on [j][stride] layout
__global__ void dot2_t(const float* __restrict__ ht, const float* __restrict__ a1,
                       const float* __restrict__ a2, float* __restrict__ o1,
                       float* __restrict__ o2, int stride)
{
    int n = blockIdx.x;
    __shared__ float s1[256], s2[256];
    float p1 = 0.f, p2 = 0.f;
    for (int j = threadIdx.x; j < HD; j += 256) {
        float hv = ht[(size_t)j * stride + n];
        p1 += hv * a1[j]; p2 += hv * a2[j];
    }
    s1[threadIdx.x] = p1; s2[threadIdx.x] = p2;
    __syncthreads();
    for (int s = 128; s > 0; s >>= 1) {
        if (threadIdx.x < s) { s1[threadIdx.x] += s1[threadIdx.x + s]; s2[threadIdx.x] += s2[threadIdx.x + s]; }
        __syncthreads();
    }
    if (threadIdx.x == 0) { o1[n] = s1[0]; o2[n] = s2[0]; }
}

// GAT aggregation on [j][stride] layout (complete cliques + self loops)
__global__ void gat_agg_t(const float* __restrict__ ht, const float* __restrict__ as,
                          const float* __restrict__ ad, const float* __restrict__ bias,
                          float* __restrict__ outt, int group, int stride, int ostride)
{
    int n = blockIdx.x;
    int base = (n / group) * group;
    __shared__ float alpha[32];
    if (threadIdx.x == 0) {
        float e[32]; float mx = -1e30f;
        for (int s = 0; s < group; s++) {
            float x = as[base + s] + ad[n];
            x = (x > 0.f) ? x : 0.2f * x;
            e[s] = x; mx = fmaxf(mx, x);
        }
        float se = 0.f;
        for (int s = 0; s < group; s++) { e[s] = expf(e[s] - mx); se += e[s]; }
        for (int s = 0; s < group; s++) alpha[s] = e[s] / se;
    }
    __syncthreads();
    for (int j = threadIdx.x; j < HD; j += 256) {
        float acc = 0.f;
        for (int s = 0; s < group; s++)
            acc += alpha[s] * ht[(size_t)j * stride + base + s];
        outt[(size_t)j * ostride + n] = acc + bias[j];
    }
}

// fusion concat into fint[k][n]
__global__ void build_fusion_t(const float* __restrict__ vt, const float* __restrict__ catot,
                               const float* __restrict__ innert, float* __restrict__ fint)
{
    int idx = blockIdx.x * 256 + threadIdx.x;
    if (idx >= H3 * NB) return;
    int k = idx / NB, n = idx - k * NB;
    float val;
    if (k < HD)            val = vt[(size_t)k * NB + n];
    else if (k < 2 * HD)   val = catot[(size_t)(k - HD) * 5 + n / 20];
    else                   val = innert[(size_t)(k - 2 * HD) * NB + n];
    fint[idx] = val;
}

// heads on ft[j][n]
__global__ void heads_t(const float* __restrict__ ft, const float* __restrict__ rw,
                        const float* __restrict__ rb, const float* __restrict__ cw,
                        const float* __restrict__ cb, float* __restrict__ out)
{
    int n = blockIdx.x;
    __shared__ float s1[256], s2[256];
    float p1 = 0.f, p2 = 0.f;
    for (int j = threadIdx.x; j < HD; j += 256) {
        float fv = ft[(size_t)j * NB + n];
        p1 += fv * rw[j]; p2 += fv * cw[j];
    }
    s1[threadIdx.x] = p1; s2[threadIdx.x] = p2;
    __syncthreads();
    for (int s = 128; s > 0; s >>= 1) {
        if (threadIdx.x < s) { s1[threadIdx.x] += s1[threadIdx.x + s]; s2[threadIdx.x] += s2[threadIdx.x + s]; }
        __syncthreads();
    }
    if (threadIdx.x == 0) {
        out[n]      = s1[0] + rb[0];
        out[NB + n] = 1.f / (1.f + expf(-(s2[0] + cb[0])));
    }
}

// =================================================================
extern "C" void kernel_launch(void* const* d_in, const int* in_sizes, int n_in,
                              void* d_out, int out_size)
{
    const float* weekly  = (const float*)d_in[0];
    const float* Wih     = (const float*)d_in[1];
    const float* Whh     = (const float*)d_in[2];
    const float* bih     = (const float*)d_in[3];
    const float* bhh     = (const float*)d_in[4];
    const float* encW    = (const float*)d_in[5];
    const float* encB    = (const float*)d_in[6];
    const float* poolW   = (const float*)d_in[7];
    const float* poolB   = (const float*)d_in[8];
    const float* innerW  = (const float*)d_in[9];
    const float* innerAs = (const float*)d_in[10];
    const float* innerAd = (const float*)d_in[11];
    const float* innerB  = (const float*)d_in[12];
    const float* catW    = (const float*)d_in[13];
    const float* catAs   = (const float*)d_in[14];
    const float* catAd   = (const float*)d_in[15];
    const float* catB    = (const float*)d_in[16];
    const float* fusW    = (const float*)d_in[17];
    const float* fusB    = (const float*)d_in[18];
    const float* regW    = (const float*)d_in[19];
    const float* regB    = (const float*)d_in[20];
    const float* clsW    = (const float*)d_in[21];
    const float* clsB    = (const float*)d_in[22];
    float* out = (float*)d_out;

    float *xp, *hst, *vt, *hpt, *innert, *catv8, *hp2t, *catot, *as_, *ad_, *as2, *ad2, *fint, *ftb;
    cudaGetSymbolAddress((void**)&xp,     g_xp);
    cudaGetSymbolAddress((void**)&hst,    g_hst);
    cudaGetSymbolAddress((void**)&vt,     g_vt);
    cudaGetSymbolAddress((void**)&hpt,    g_hpt);
    cudaGetSymbolAddress((void**)&innert, g_innert);
    cudaGetSymbolAddress((void**)&catv8,  g_catv8);
    cudaGetSymbolAddress((void**)&hp2t,   g_hp2t);
    cudaGetSymbolAddress((void**)&catot,  g_catot);
    cudaGetSymbolAddress((void**)&as_,    g_as);
    cudaGetSymbolAddress((void**)&ad_,    g_ad);
    cudaGetSymbolAddress((void**)&as2,    g_as2);
    cudaGetSymbolAddress((void**)&ad2,    g_ad2);
    cudaGetSymbolAddress((void**)&fint,   g_fint);
    cudaGetSymbolAddress((void**)&ftb,    g_ft);

    // 1) xp = weekly(51200,256) @ Wih^T + bih
    gemm_nt<<<dim3(H3 / 128, (NB * TT) / 128), 256>>>(weekly, Wih, bih, xp, NB * TT, H3, IND, 0);

    // 2) persistent GRU (all 512 steps in one launch)
    cudaFuncSetAttribute(gru_persist, cudaFuncAttributeMaxDynamicSharedMemorySize, 196608);
    gru_persist<<<128, 200, 196608>>>(xp, Whh, bhh, hst);

    // 3) S(512 x 102400) = encW @ H + encB[u]  (reuse xp buffer)
    gemm_nn<<<dim3(NDB / 128, TT / 128), 256>>>(encW, hst, encB, xp, TT, NDB, TT, 0);

    // 4) vt[j] = softmax-over-u(S) . H
    att_reduce_flat<<<NDB / 256, 256>>>(xp, hst, vt);

    // 5) inner GAT: hpt = innerW @ vt  (M=1024,N=100,K=1024)
    gemm_nn<<<dim3(1, HD / 128), 256>>>(innerW, vt, nullptr, hpt, HD, NB, HD, 0);
    dot2_t<<<NB, 256>>>(hpt, innerAs, innerAd, as_, ad_, NB);
    gat_agg_t<<<NB, 256>>>(hpt, as_, ad_, innerB, innert, 20, NB, NB);

    // 6) pool 20 stocks -> category vectors (padded to stride 8)
    pool_att_t<<<dim3(8, HD / 256), 256>>>(vt, poolW, poolB, catv8);

    // 7) category GAT: hp2t = catW @ catv8  (N=8 padded)
    gemm_nn<<<dim3(1, HD / 128), 256>>>(catW, catv8, nullptr, hp2t, HD, 8, HD, 0);
    dot2_t<<<5, 256>>>(hp2t, catAs, catAd, as2, ad2, 8);
    gat_agg_t<<<5, 256>>>(hp2t, as2, ad2, catB, catot, 5, 8, 5);

    // 8) fusion: fint[k][n], ft = relu(fusW @ fint + fusB)
    build_fusion_t<<<(H3 * NB + 255) / 256, 256>>>(vt, catot, innert, fint);
    gemm_nn<<<dim3(1, HD / 128), 256>>>(fusW, fint, fusB, ftb, HD, NB, H3, 1);

    // 9) heads
    heads_t<<<NB, 256>>>(ftb, regW, regB, clsW, clsB, out);
}